// round 6
// baseline (speedup 1.0000x reference)
#include <cuda_runtime.h>
#include <cuda_bf16.h>
#include <stdint.h>

#define NN   100000
#define EE   1600000
#define CIN  128
#define CHID 64
#define COUT 40

// Scratch (static __device__ arrays — no allocation allowed)
__device__ int    g_oddnz;
__device__ int    g_intok;
__device__ int    g_fltok;
__device__ int    g_dtype;          // 0=int32, 1=int64, 2=float32
__device__ int    g_cnt[NN];        // in-degree (excl self loop)
__device__ int    g_rowstart[NN];   // CSR row offsets
__device__ int    g_fillpos[NN];    // atomic cursors for CSR fill
__device__ int    g_bsum[128];      // block sums for scan
__device__ int2   g_epk[EE];        // CSR entry: {src, __float_as_int(dinv[src])}
__device__ float  g_dinv[NN];
__device__ float4 g_h1 [(size_t)NN * CHID / 4];
__device__ float4 g_hag[(size_t)NN * CHID / 4];
__device__ float4 g_h2 [(size_t)NN * COUT / 4];

#define SCAN_BLK 1024
#define PROBE_N  4096

// ---------------------------------------------------------------------------
// packed f32x2 FMA: d = a * b + d
__device__ __forceinline__ void ffma2(unsigned long long& d,
                                      unsigned long long a,
                                      unsigned long long b) {
    asm volatile("fma.rn.f32x2 %0, %1, %2, %0;" : "+l"(d) : "l"(a), "l"(b));
}
__device__ __forceinline__ unsigned long long pack2(float lo, float hi) {
    unsigned long long r;
    asm("mov.b64 %0, {%1, %2};" : "=l"(r) : "f"(lo), "f"(hi));
    return r;
}

// decode one node id from the raw edge buffer under the probed dtype
__device__ __forceinline__ int decode_id(const void* p, size_t idx, int dt, int n) {
    int v;
    if (dt == 1)      v = (int)((const long long*)p)[idx];
    else if (dt == 2) v = (int)((const float*)p)[idx];
    else              v = ((const int*)p)[idx];
    return min(max(v, 0), n - 1);
}

// ---------------------------------------------------------------------------
__global__ void k_init(int n) {
    int i = blockIdx.x * blockDim.x + threadIdx.x;
    if (i == 0) { g_oddnz = 0; g_intok = 0; g_fltok = 0; g_dtype = 0; }
    if (i < n) g_cnt[i] = 0;
}

__global__ void k_probe(const unsigned* __restrict__ p, int npairs, int n) {
    int i = blockIdx.x * blockDim.x + threadIdx.x;
    if (i >= npairs) return;
    unsigned lo = p[2 * i];
    unsigned hi = p[2 * i + 1];
    if (hi != 0) atomicAdd(&g_oddnz, 1);
    int iv = (int)lo;
    if (iv >= 0 && iv < n) atomicAdd(&g_intok, 1);
    float f = __int_as_float(iv);
    if (f >= 0.0f && f < (float)n && f == floorf(f)) atomicAdd(&g_fltok, 1);
}

__global__ void k_decide() {
    if (g_oddnz == 0)            g_dtype = 1;
    else if (g_fltok > g_intok)  g_dtype = 2;
    else                         g_dtype = 0;
}

// decode dst + count in-degree
__global__ void k_count(const void* __restrict__ p, int E, int n) {
    int e = blockIdx.x * blockDim.x + threadIdx.x;
    if (e >= E) return;
    int d = decode_id(p, (size_t)E + e, g_dtype, n);
    atomicAdd(&g_cnt[d], 1);
}

// per-block exclusive scan
__global__ void k_scan1(int n) {
    __shared__ int s[2][SCAN_BLK];
    int t = threadIdx.x;
    int idx = blockIdx.x * SCAN_BLK + t;
    int v = (idx < n) ? g_cnt[idx] : 0;
    s[0][t] = v;
    __syncthreads();
    int cur = 0;
    for (int off = 1; off < SCAN_BLK; off <<= 1) {
        int nxt = cur ^ 1;
        int add = (t >= off) ? s[cur][t - off] : 0;
        s[nxt][t] = s[cur][t] + add;
        __syncthreads();
        cur = nxt;
    }
    if (idx < n) g_rowstart[idx] = s[cur][t] - v;
    if (t == SCAN_BLK - 1) g_bsum[blockIdx.x] = s[cur][t];
}

// parallel exclusive scan of <=128 block sums (one block of 128 threads)
__global__ void k_scan2(int nb) {
    __shared__ int s[2][128];
    int t = threadIdx.x;
    int v = (t < nb) ? g_bsum[t] : 0;
    s[0][t] = v;
    __syncthreads();
    int cur = 0;
    for (int off = 1; off < 128; off <<= 1) {
        int nxt = cur ^ 1;
        int add = (t >= off) ? s[cur][t - off] : 0;
        s[nxt][t] = s[cur][t] + add;
        __syncthreads();
        cur = nxt;
    }
    if (t < nb) g_bsum[t] = s[cur][t] - v;   // exclusive
}

// add block offsets; init fill cursors; dinv = rsqrt(deg+1)
__global__ void k_scan3(int n) {
    int idx = blockIdx.x * blockDim.x + threadIdx.x;
    if (idx >= n) return;
    int rs = g_rowstart[idx] + g_bsum[idx / SCAN_BLK];
    g_rowstart[idx] = rs;
    g_fillpos[idx]  = rs;
    g_dinv[idx] = rsqrtf((float)g_cnt[idx] + 1.0f);
}

// CSR fill: store {src, dinv[src]} packed (kills a dependent load in gather)
__global__ void k_fill(const void* __restrict__ p, int E, int n) {
    int e = blockIdx.x * blockDim.x + threadIdx.x;
    if (e >= E) return;
    int dt = g_dtype;
    int s = decode_id(p, (size_t)e, dt, n);
    int d = decode_id(p, (size_t)E + e, dt, n);
    int pos = atomicAdd(&g_fillpos[d], 1);
    if (pos >= 0 && pos < E)
        g_epk[pos] = make_int2(s, __float_as_int(g_dinv[s]));
}

// ---------------------------------------------------------------------------
// GEMM1: g_h1 = x @ W1  (M x 128)@(128 x 64). One thread per row, FFMA2 inner.
__global__ void __launch_bounds__(256) k_gemm1(const float* __restrict__ x,
                                               const float* __restrict__ W, int M) {
    __shared__ __align__(16) float Ws[CIN * CHID];
    for (int i = threadIdx.x; i < CIN * CHID; i += blockDim.x) Ws[i] = W[i];
    __syncthreads();

    int row = blockIdx.x * blockDim.x + threadIdx.x;
    if (row >= M) return;

    unsigned long long acc[CHID / 2];
    #pragma unroll
    for (int c = 0; c < CHID / 2; c++) acc[c] = 0ull;

    const float4* a4 = (const float4*)(x + (size_t)row * CIN);
    for (int k4 = 0; k4 < CIN / 4; k4++) {
        float4 xv = __ldg(a4 + k4);
        #pragma unroll
        for (int j = 0; j < 4; j++) {
            float xk = (j == 0) ? xv.x : (j == 1) ? xv.y : (j == 2) ? xv.z : xv.w;
            unsigned long long xp = pack2(xk, xk);
            const unsigned long long* w2 =
                (const unsigned long long*)&Ws[(4 * k4 + j) * CHID];
            #pragma unroll
            for (int c = 0; c < CHID / 2; c++) ffma2(acc[c], xp, w2[c]);
        }
    }
    ulonglong2* o = (ulonglong2*)&g_h1[(size_t)row * (CHID / 4)];
    #pragma unroll
    for (int c = 0; c < CHID / 4; c++)
        o[c] = make_ulonglong2(acc[2 * c], acc[2 * c + 1]);
}

// GEMM2: g_h2 = relu(g_hag) @ W2, FFMA2 inner.
__global__ void __launch_bounds__(256) k_gemm2(const float* __restrict__ W, int M) {
    __shared__ __align__(16) float Ws[CHID * COUT];
    for (int i = threadIdx.x; i < CHID * COUT; i += blockDim.x) Ws[i] = W[i];
    __syncthreads();

    int row = blockIdx.x * blockDim.x + threadIdx.x;
    if (row >= M) return;

    unsigned long long acc[COUT / 2];
    #pragma unroll
    for (int c = 0; c < COUT / 2; c++) acc[c] = 0ull;

    const float4* a4 = (const float4*)&g_hag[(size_t)row * (CHID / 4)];
    for (int k4 = 0; k4 < CHID / 4; k4++) {
        float4 xv = a4[k4];
        xv.x = fmaxf(xv.x, 0.0f); xv.y = fmaxf(xv.y, 0.0f);
        xv.z = fmaxf(xv.z, 0.0f); xv.w = fmaxf(xv.w, 0.0f);
        #pragma unroll
        for (int j = 0; j < 4; j++) {
            float xk = (j == 0) ? xv.x : (j == 1) ? xv.y : (j == 2) ? xv.z : xv.w;
            unsigned long long xp = pack2(xk, xk);
            const unsigned long long* w2 =
                (const unsigned long long*)&Ws[(4 * k4 + j) * COUT];
            #pragma unroll
            for (int c = 0; c < COUT / 2; c++) ffma2(acc[c], xp, w2[c]);
        }
    }
    ulonglong2* o = (ulonglong2*)&g_h2[(size_t)row * (COUT / 4)];
    #pragma unroll
    for (int c = 0; c < COUT / 4; c++)
        o[c] = make_ulonglong2(acc[2 * c], acc[2 * c + 1]);
}

// ---------------------------------------------------------------------------
// Gather layer 1 — one warp per node. Lanes: half = lane>>4 processes edges
// j = half, half+2, ...; c = lane&15 is the float4 chunk. Uniform trip count
// across the warp; 2 independent edge chains in flight.
__global__ void __launch_bounds__(256) k_gather1(const float* __restrict__ b1, int M, int E) {
    int warp = threadIdx.y;                       // 0..7
    int i = blockIdx.x * 8 + warp;
    if (i >= M) return;
    int lane = threadIdx.x;                       // 0..31
    int half = lane >> 4;                         // 0/1
    int c    = lane & 15;                         // chunk 0..15

    float di = g_dinv[i];
    int start = g_rowstart[i];
    int num   = min(g_cnt[i], E - start);

    float4 acc = make_float4(0.f, 0.f, 0.f, 0.f);
    #pragma unroll 2
    for (int j = half; j < num; j += 2) {
        int2 pk = g_epk[start + j];
        float w = __int_as_float(pk.y) * di;
        float4 u = g_h1[(size_t)pk.x * (CHID/4) + c];
        acc.x += u.x * w; acc.y += u.y * w; acc.z += u.z * w; acc.w += u.w * w;
    }
    // combine the two halves
    acc.x += __shfl_xor_sync(0xffffffffu, acc.x, 16);
    acc.y += __shfl_xor_sync(0xffffffffu, acc.y, 16);
    acc.z += __shfl_xor_sync(0xffffffffu, acc.z, 16);
    acc.w += __shfl_xor_sync(0xffffffffu, acc.w, 16);
    if (half == 0) {
        float4 v = g_h1[(size_t)i * (CHID/4) + c];
        float4 b = ((const float4*)b1)[c];
        float s = di * di;
        acc.x += v.x * s + b.x; acc.y += v.y * s + b.y;
        acc.z += v.z * s + b.z; acc.w += v.w * s + b.w;
        g_hag[(size_t)i * (CHID/4) + c] = acc;
    }
}

// Gather layer 2 — one warp per node, 3 edge-groups of 10 chunk-lanes.
__global__ void __launch_bounds__(256) k_gather2(const float* __restrict__ b2,
                                                 float* __restrict__ out, int M, int E) {
    int warp = threadIdx.y;
    int i = blockIdx.x * 8 + warp;
    if (i >= M) return;
    int lane = threadIdx.x;
    int half = lane / 10;                         // 0,1,2 (3 = idle lanes 30,31)
    int c    = lane - half * 10;                  // chunk 0..9

    float di = g_dinv[i];
    int start = g_rowstart[i];
    int num   = min(g_cnt[i], E - start);

    float4 acc = make_float4(0.f, 0.f, 0.f, 0.f);
    if (half < 3) {
        #pragma unroll 2
        for (int j = half; j < num; j += 3) {
            int2 pk = g_epk[start + j];
            float w = __int_as_float(pk.y) * di;
            float4 u = g_h2[(size_t)pk.x * (COUT/4) + c];
            acc.x += u.x * w; acc.y += u.y * w; acc.z += u.z * w; acc.w += u.w * w;
        }
    }
    // combine the three groups into lanes 0..9
    int l1 = (lane < 10) ? lane + 10 : lane;
    int l2 = (lane < 10) ? lane + 20 : lane;
    float ax = acc.x, ay = acc.y, az = acc.z, aw = acc.w;
    acc.x = ax + __shfl_sync(0xffffffffu, ax, l1) + __shfl_sync(0xffffffffu, ax, l2);
    acc.y = ay + __shfl_sync(0xffffffffu, ay, l1) + __shfl_sync(0xffffffffu, ay, l2);
    acc.z = az + __shfl_sync(0xffffffffu, az, l1) + __shfl_sync(0xffffffffu, az, l2);
    acc.w = aw + __shfl_sync(0xffffffffu, aw, l1) + __shfl_sync(0xffffffffu, aw, l2);
    if (lane < 10) {
        float4 v = g_h2[(size_t)i * (COUT/4) + c];
        float4 b = ((const float4*)b2)[c];
        float s = di * di;
        acc.x += v.x * s + b.x; acc.y += v.y * s + b.y;
        acc.z += v.z * s + b.z; acc.w += v.w * s + b.w;
        ((float4*)out)[(size_t)i * (COUT/4) + c] = acc;
    }
}

// ---------------------------------------------------------------------------
extern "C" void kernel_launch(void* const* d_in, const int* in_sizes, int n_in,
                              void* d_out, int out_size) {
    int M = out_size / COUT;                 // 100000

    const float* x  = nullptr;
    const float* W1 = nullptr;
    const float* b1 = nullptr;
    const float* W2 = nullptr;
    const float* b2 = nullptr;
    const void*  ei = nullptr;
    int eiElems = 0;
    for (int i = 0; i < n_in; i++) {
        int s = in_sizes[i];
        if      (s == M * CIN)      x  = (const float*)d_in[i];
        else if (s == CIN * CHID)   W1 = (const float*)d_in[i];
        else if (s == CHID)         b1 = (const float*)d_in[i];
        else if (s == CHID * COUT)  W2 = (const float*)d_in[i];
        else if (s == COUT)         b2 = (const float*)d_in[i];
        else { ei = d_in[i]; eiElems = s; }
    }
    if (!x || !W1 || !b1 || !W2 || !b2 || !ei) return;

    int E = eiElems / 2;
    if (E > EE) E = EE;
    if (M > NN) M = NN;
    int nb = (M + SCAN_BLK - 1) / SCAN_BLK;

    float* out = (float*)d_out;

    k_init<<<(M + 255) / 256, 256>>>(M);
    {
        int npairs = (E < PROBE_N) ? E : PROBE_N;
        k_probe<<<(npairs + 255) / 256, 256>>>((const unsigned*)ei, npairs, M);
    }
    k_decide<<<1, 1>>>();
    k_count<<<(E + 255) / 256, 256>>>(ei, E, M);
    k_scan1<<<nb, SCAN_BLK>>>(M);
    k_scan2<<<1, 128>>>(nb);
    k_scan3<<<(M + 255) / 256, 256>>>(M);
    k_fill<<<(E + 255) / 256, 256>>>(ei, E, M);

    // layer 1
    k_gemm1<<<(M + 255) / 256, 256>>>(x, W1, M);
    {
        dim3 bd(32, 8);
        k_gather1<<<(M + 7) / 8, bd>>>(b1, M, E);
    }

    // layer 2
    k_gemm2<<<(M + 255) / 256, 256>>>(W2, M);
    {
        dim3 bd(32, 8);
        k_gather2<<<(M + 7) / 8, bd>>>(b2, out, M, E);
    }
}